// round 12
// baseline (speedup 1.0000x reference)
#include <cuda_runtime.h>
#include <math.h>

// Problem constants
#define B_    2
#define T_    64
#define BT_   128
#define CIN_  16
#define HW_   4096
#define OC_   64
#define NH_   8
#define DD_   32768
#define BH_   16
#define NCHUNK_ 32      // score d-chunks (d=1024 each)

// ---------------- scratch (device globals) -----------------------------------
__device__ float g_q[(size_t)BH_ * T_ * DD_];            // 128 MB
__device__ float g_k[(size_t)BH_ * T_ * DD_];            // 128 MB
__device__ float g_v[(size_t)BH_ * T_ * DD_];            // 128 MB
__device__ float g_Sp[(size_t)BH_ * NCHUNK_ * T_ * T_];  // 8.4 MB
__device__ float g_att[(size_t)BH_ * T_ * T_];           // 256 KB
__device__ float g_y[(size_t)BT_ * OC_ * HW_];           // 128 MB

__device__ __forceinline__ unsigned to_tf32(float x) {
    unsigned r;
    asm("cvt.rna.tf32.f32 %0, %1;" : "=r"(r) : "f"(x));
    return r;
}
__device__ __forceinline__ float to_tf32f(float x) {
    return __uint_as_float(to_tf32(x));
}

__device__ __forceinline__ void mma_tf32(float& d0, float& d1, float& d2, float& d3,
                                         unsigned a0, unsigned a1, unsigned a2, unsigned a3,
                                         unsigned b0, unsigned b1) {
    asm volatile(
        "mma.sync.aligned.m16n8k8.row.col.f32.tf32.tf32.f32 "
        "{%0,%1,%2,%3},{%4,%5,%6,%7},{%8,%9},{%0,%1,%2,%3};"
        : "+f"(d0), "+f"(d1), "+f"(d2), "+f"(d3)
        : "r"(a0), "r"(a1), "r"(a2), "r"(a3), "r"(b0), "r"(b1));
}

// K-dimension ordering for conv GEMMs: k = r*16 + c  (r = 3x3 tap, c = channel)
// -> c = k & 15, r = k >> 4, kh = r/3 = (r*11)>>5 (exact for r<9), kw = r - 3*kh.

// ============================================================================
// Kernel A: fused QKV 3x3 conv via TF32 tensor cores.
// M=256 (4 image rows) x 96 oc; warp tile M=64, N=48. grid (4, 128, 2);
// block loops 4 yi of 4 rows. ws[144][104]; xs[16c][6r][66] (region 6528 for
// epilogue transpose buffer tb[oc96][row4][xx16] stride 68, conflict-free).
// Epilogue: smem transpose -> vectorized STG.128 (replaces 96 scattered STG.32).
// smem 86.4 KB -> 2 blocks/SM. 8 warps: wm = warp&3 (row), wn = warp>>2.
// ============================================================================
#define WSTR_ 104
#define NXQ_ (16 * 6 * 66)   // 6336 staged floats
#define XSZ_ 6528            // xs region (>= max(NXQ_, 96*68))
__global__ __launch_bounds__(256, 2) void a_qkv_tc(
    const float* __restrict__ x,
    const float* __restrict__ wq, const float* __restrict__ bq,
    const float* __restrict__ wk, const float* __restrict__ bk,
    const float* __restrict__ wv, const float* __restrict__ bv)
{
    extern __shared__ float sm[];
    float* ws = sm;                  // 144*104 = 14976
    float* xs = sm + 14976;          // XSZ_ = 6528
    float* bs = xs + XSZ_;           // 96

    const int tid  = threadIdx.x;
    const int bt   = blockIdx.y;
    const int half = blockIdx.z;     // 0: oc 0..95, 1: oc 96..191
    const float* xin = x + (size_t)bt * CIN_ * HW_;

    // stage this half's weights once, K-reordered: ws[r*16+c][oc_l]
    {
        int oc_l = tid / 144, k = tid % 144;
        for (int idx = tid; idx < 96 * 144; idx += 256) {
            const int r = k >> 4, c = k & 15;
            const int ocg = half * 96 + oc_l;
            const float* wsrc = (ocg < 64) ? wq : ((ocg < 128) ? wk : wv);
            ws[k * WSTR_ + oc_l] = to_tf32f(wsrc[(ocg & 63) * 144 + c * 9 + r]);
            k += 112; ++oc_l;
            if (k >= 144) { k -= 144; ++oc_l; }
        }
    }
    if (tid < 96) {
        const int ocg = half * 96 + tid;
        bs[tid] = (ocg < 64) ? bq[ocg] : ((ocg < 128) ? bk[ocg - 64] : bv[ocg - 128]);
    }

    const int warp = tid >> 5, lane = tid & 31;
    const int wm = warp & 3, wn = warp >> 2;     // wm: row 0..3, wn: 0..1 (48 oc)
    const int lg = lane >> 2, lt = lane & 3;
    const int b = bt >> 6, t = bt & 63;

    // initial (c, r, cc) decomposition of tid over [16c][6r][66]
    const int c0_ = tid / 396, rem0_ = tid % 396;
    const int r0_ = rem0_ / 66, cc0_ = rem0_ % 66;

    for (int yi = 0; yi < 4; yi++) {
        const int y0 = blockIdx.x * 16 + yi * 4;   // 0..60
        __syncthreads();
        // stage x tile rows y0-1 .. y0+4: incremental indices, step 256 = 3*66+58
        {
            int c = c0_, r = r0_, cc = cc0_;
            for (int idx = tid; idx < NXQ_; idx += 256) {
                const int gy = y0 - 1 + r, gx = cc - 1;
                float v = 0.f;
                if (gy >= 0 && gy < 64 && gx >= 0 && gx < 64) v = xin[c * HW_ + gy * 64 + gx];
                xs[idx] = to_tf32f(v);
                cc += 58; r += 3;
                if (cc >= 66) { cc -= 66; ++r; }
                if (r >= 6)   { r -= 6;  ++c; }
            }
        }
        __syncthreads();

        float acc[4][6][4];
        #pragma unroll
        for (int m = 0; m < 4; m++)
            #pragma unroll
            for (int n = 0; n < 6; n++)
                #pragma unroll
                for (int r = 0; r < 4; r++) acc[m][n][r] = 0.f;

        #pragma unroll
        for (int kc = 0; kc < 18; kc++) {
            const int k1 = kc * 8 + lt;
            const int k2 = k1 + 4;
            const int c1 = k1 & 15, r1 = k1 >> 4;
            const int c2 = k2 & 15, r2 = k2 >> 4;
            const int t1 = (r1 * 11) >> 5;         // r1/3
            const int t2 = (r2 * 11) >> 5;
            const int aA1 = c1 * 396 + (wm + t1) * 66 + (r1 - 3 * t1) + lg;
            const int aA2 = c2 * 396 + (wm + t2) * 66 + (r2 - 3 * t2) + lg;

            unsigned bfr[6][2];
            #pragma unroll
            for (int n = 0; n < 6; n++) {
                const int oc_l = wn * 48 + n * 8 + lg;
                bfr[n][0] = __float_as_uint(ws[k1 * WSTR_ + oc_l]);
                bfr[n][1] = __float_as_uint(ws[k2 * WSTR_ + oc_l]);
            }
            #pragma unroll
            for (int m = 0; m < 4; m++) {
                const int xo = m * 16;
                const unsigned a0 = __float_as_uint(xs[aA1 + xo]);
                const unsigned a1 = __float_as_uint(xs[aA1 + xo + 8]);
                const unsigned a2 = __float_as_uint(xs[aA2 + xo]);
                const unsigned a3 = __float_as_uint(xs[aA2 + xo + 8]);
                #pragma unroll
                for (int n = 0; n < 6; n++)
                    mma_tf32(acc[m][n][0], acc[m][n][1], acc[m][n][2], acc[m][n][3],
                             a0, a1, a2, a3, bfr[n][0], bfr[n][1]);
            }
        }

        // ---- epilogue via smem transpose: xs is dead until next yi staging.
        // tb[oc96][row4][xx16], stride 68 per oc (float4-aligned, dump banks
        // 8lt+lg conflict-free). One pass per m-chunk of 16 xx.
        float* tb = xs;
        #pragma unroll
        for (int p = 0; p < 4; p++) {
            __syncthreads();   // prior pass reads done (p=0: mma xs reads done)
            #pragma unroll
            for (int n = 0; n < 6; n++) {
                const int ocA = wn * 48 + n * 8 + 2 * lt;
                #pragma unroll
                for (int r = 0; r < 4; r++) {
                    const int oc_l = ocA + (r & 1);
                    const int xxl  = lg + ((r & 2) ? 8 : 0);
                    tb[oc_l * 68 + wm * 16 + xxl] = acc[p][n][r] + bs[oc_l];
                }
            }
            __syncthreads();
            // cooperative vectorized store: 96oc x 4row x 4 float4 = 1536
            #pragma unroll
            for (int it = 0; it < 6; it++) {
                const int i   = tid + it * 256;
                const int oc_l = i >> 4;
                const int row  = (i >> 2) & 3;
                const int jj   = (i & 3) << 2;
                const float4 vv = *(const float4*)&tb[oc_l * 68 + row * 16 + jj];
                const int ocg = half * 96 + oc_l;
                float* dst = (ocg < 64) ? g_q : ((ocg < 128) ? g_k : g_v);
                const int ol = ocg & 63;
                const size_t addr = ((size_t)((b * 8 + (ol >> 3)) * 64 + t)) * DD_
                                  + (size_t)(ol & 7) * 4096
                                  + (size_t)(y0 + row) * 64 + p * 16 + jj;
                *(float4*)&dst[addr] = vv;
            }
        }
    }
}

// ============================================================================
// Kernel B: output 3x3 conv (64 -> 64) via TF32 tensor cores.
// Full weight panel ws[576][72] staged once; xs double-buffered with register
// prefetch. Epilogue (at cc==3): smem transpose in dead xcur buffer ->
// vectorized STG.128. grid (4, 128). 8 warps: wm = warp&3, wn = warp>>2.
// ============================================================================
#define NX_ (16 * 6 * 66)    // 6336
__global__ __launch_bounds__(256) void b_convo_tc(
    const float* __restrict__ wo, const float* __restrict__ bo, float* __restrict__ out)
{
    extern __shared__ float sm[];
    float* ws = sm;                  // 576*72 = 41472
    float* xs = sm + 41472;          // 2 * 6336 = 12672
    float* bs = xs + 2 * NX_;        // 64

    const int tid = threadIdx.x;
    const int bt  = blockIdx.y;
    const float* yin = g_y + (size_t)bt * OC_ * HW_;

    // stage full weight panel once (incremental (oc, kg, cc2, kl) over 36864)
    {
        int oc = tid / 576, kg = tid % 576;
        int cc2 = kg / 144, kl = kg % 144;
        for (int idx = tid; idx < 64 * 576; idx += 256) {
            const int r = kl >> 4, cl = kl & 15;
            ws[kg * 72 + oc] = to_tf32f(wo[(size_t)oc * 576 + (cc2 * 16 + cl) * 9 + r]);
            kg += 256; kl += 112; cc2 += 1;
            if (kl >= 144) { kl -= 144; ++cc2; }
            if (kg >= 576) { kg -= 576; ++oc; cc2 -= 4; }
        }
    }
    if (tid < 64) bs[tid] = bo[tid];

    const int warp = tid >> 5, lane = tid & 31;
    const int wm = warp & 3, wn = warp >> 2;
    const int lg = lane >> 2, lt = lane & 3;

    // initial (c, r, cc) decomposition of tid over [16c][6r][66]
    const int c0_ = tid / 396, rem0_ = tid % 396;
    const int r0_ = rem0_ / 66, cc0_ = rem0_ % 66;

    // initial stage: s = 0 (yt=0, cc=0) into buffer 0
    {
        const int y0 = blockIdx.x * 16;
        int c = c0_, r = r0_, cc = cc0_;
        for (int idx = tid; idx < NX_; idx += 256) {
            const int gy = y0 - 1 + r, gx = cc - 1;
            float v = 0.f;
            if (gy >= 0 && gy < 64 && gx >= 0 && gx < 64)
                v = yin[c * HW_ + gy * 64 + gx];
            xs[idx] = to_tf32f(v);
            cc += 58; r += 3;
            if (cc >= 66) { cc -= 66; ++r; }
            if (r >= 6)   { r -= 6;  ++c; }
        }
    }
    __syncthreads();

    float acc[4][4][4];

    for (int s = 0; s < 16; s++) {
        const int yt = s >> 2, cc = s & 3;
        float* xcur = xs + (s & 1) * NX_;
        float* xnxt = xs + ((s + 1) & 1) * NX_;

        float pre[25];
        if (s < 15) {
            const int s2 = s + 1;
            const int yt2 = s2 >> 2, cc2 = s2 & 3;
            const int y0n = blockIdx.x * 16 + yt2 * 4;
            int cI = c0_, rI = r0_, ccI = cc0_;
            int idx = tid;
            #pragma unroll
            for (int j = 0; j < 25; j++) {
                float v = 0.f;
                if (idx < NX_) {
                    const int gy = y0n - 1 + rI, gx = ccI - 1;
                    if (gy >= 0 && gy < 64 && gx >= 0 && gx < 64)
                        v = yin[(cc2 * 16 + cI) * HW_ + gy * 64 + gx];
                }
                pre[j] = v;
                idx += 256;
                ccI += 58; rI += 3;
                if (ccI >= 66) { ccI -= 66; ++rI; }
                if (rI >= 6)   { rI -= 6;  ++cI; }
            }
        }

        if (cc == 0) {
            #pragma unroll
            for (int m = 0; m < 4; m++)
                #pragma unroll
                for (int n = 0; n < 4; n++)
                    #pragma unroll
                    for (int r = 0; r < 4; r++) acc[m][n][r] = 0.f;
        }

        #pragma unroll
        for (int kc = 0; kc < 18; kc++) {
            const int k1 = kc * 8 + lt;
            const int k2 = k1 + 4;
            const int c1 = k1 & 15, r1 = k1 >> 4;
            const int c2 = k2 & 15, r2 = k2 >> 4;
            const int t1 = (r1 * 11) >> 5;         // r1/3
            const int t2 = (r2 * 11) >> 5;
            const int aA1 = c1 * 396 + (wm + t1) * 66 + (r1 - 3 * t1) + lg;
            const int aA2 = c2 * 396 + (wm + t2) * 66 + (r2 - 3 * t2) + lg;
            const int kg1 = cc * 144 + k1, kg2 = cc * 144 + k2;

            unsigned bfr[4][2];
            #pragma unroll
            for (int n = 0; n < 4; n++) {
                const int oc = wn * 32 + n * 8 + lg;
                bfr[n][0] = __float_as_uint(ws[kg1 * 72 + oc]);
                bfr[n][1] = __float_as_uint(ws[kg2 * 72 + oc]);
            }
            #pragma unroll
            for (int m = 0; m < 4; m++) {
                const int xo = m * 16;
                const unsigned a0 = __float_as_uint(xcur[aA1 + xo]);
                const unsigned a1 = __float_as_uint(xcur[aA1 + xo + 8]);
                const unsigned a2 = __float_as_uint(xcur[aA2 + xo]);
                const unsigned a3 = __float_as_uint(xcur[aA2 + xo + 8]);
                #pragma unroll
                for (int n = 0; n < 4; n++)
                    mma_tf32(acc[m][n][0], acc[m][n][1], acc[m][n][2], acc[m][n][3],
                             a0, a1, a2, a3, bfr[n][0], bfr[n][1]);
            }
        }

        if (s < 15) {
            #pragma unroll
            for (int j = 0; j < 25; j++) {
                const int idx = tid + j * 256;
                if (idx < NX_) xnxt[idx] = to_tf32f(pre[j]);
            }
        }
        __syncthreads();

        if (cc == 3) {
            // epilogue via smem transpose in dead xcur: tb[oc64][row4][xx16],
            // stride 68 (float4-aligned; dump banks 8lt+lg conflict-free).
            float* tb = xcur;
            const int ybase = blockIdx.x * 16 + yt * 4;
            #pragma unroll
            for (int p = 0; p < 4; p++) {
                __syncthreads();
                #pragma unroll
                for (int n = 0; n < 4; n++) {
                    const int ocA = wn * 32 + n * 8 + 2 * lt;
                    #pragma unroll
                    for (int r = 0; r < 4; r++) {
                        const int oc  = ocA + (r & 1);
                        const int xxl = lg + ((r & 2) ? 8 : 0);
                        tb[oc * 68 + wm * 16 + xxl] = acc[p][n][r] + bs[oc];
                    }
                }
                __syncthreads();
                // 64oc x 4row x 4 float4 = 1024
                #pragma unroll
                for (int it = 0; it < 4; it++) {
                    const int i   = tid + it * 256;
                    const int oc  = i >> 4;
                    const int row = (i >> 2) & 3;
                    const int jj  = (i & 3) << 2;
                    const float4 vv = *(const float4*)&tb[oc * 68 + row * 16 + jj];
                    const size_t addr = ((size_t)(bt * 64 + oc)) * 4096
                                      + (size_t)(ybase + row) * 64 + p * 16 + jj;
                    *(float4*)&out[addr] = vv;
                }
            }
            __syncthreads();   // protect tb before s+1's commit writes this buffer
        }
    }
}

// ============================================================================
// Kernel C: partial scores via TF32 mma. Sp[bh][chunk][64][64], d-chunk 1024.
// Natural [row][dd] stride-132 staging, float4 coalesced, conflict-free.
// smem 67.6 KB -> 2 blocks/SM. grid (32, 16), 256 threads.
// ============================================================================
__global__ __launch_bounds__(256, 2) void c_scores_tc()
{
    extern __shared__ float sm[];
    float* qs = sm;            // 64*132 = 8448
    float* kn = sm + 8448;     // 64*132 = 8448

    const int tid   = threadIdx.x;
    const int chunk = blockIdx.x;   // 0..31
    const int bh    = blockIdx.y;
    const int warp = tid >> 5, lane = tid & 31;
    const int wm = warp & 1, wn = warp >> 1;        // wn 0..3
    const int lg = lane >> 2, lt = lane & 3;

    float acc[2][2][4];
    #pragma unroll
    for (int m = 0; m < 2; m++)
        #pragma unroll
        for (int n = 0; n < 2; n++)
            #pragma unroll
            for (int r = 0; r < 4; r++) acc[m][n][r] = 0.f;

    for (int sub = 0; sub < 8; sub++) {
        const int d0 = chunk * 1024 + sub * 128;
        __syncthreads();
        for (int i = tid; i < 2048; i += 256) {      // float4 granularity
            const int row = i >> 5, dd = (i & 31) << 2;
            const size_t g = ((size_t)(bh * T_ + row)) * DD_ + d0 + dd;
            const float4 q4 = *(const float4*)&g_q[g];
            const float4 k4 = *(const float4*)&g_k[g];
            *(float4*)&qs[row * 132 + dd] = make_float4(
                to_tf32f(q4.x), to_tf32f(q4.y), to_tf32f(q4.z), to_tf32f(q4.w));
            *(float4*)&kn[row * 132 + dd] = make_float4(
                to_tf32f(k4.x), to_tf32f(k4.y), to_tf32f(k4.z), to_tf32f(k4.w));
        }
        __syncthreads();

        #pragma unroll
        for (int ks8 = 0; ks8 < 16; ks8++) {
            const int k1 = ks8 * 8 + lt;
            unsigned bfr[2][2];
            #pragma unroll
            for (int n = 0; n < 2; n++) {
                const int n0 = wn * 16 + n * 8 + lg;
                bfr[n][0] = __float_as_uint(kn[n0 * 132 + k1]);
                bfr[n][1] = __float_as_uint(kn[n0 * 132 + k1 + 4]);
            }
            #pragma unroll
            for (int m = 0; m < 2; m++) {
                const int m0 = wm * 32 + m * 16 + lg;
                const unsigned a0 = __float_as_uint(qs[m0 * 132 + k1]);
                const unsigned a1 = __float_as_uint(qs[(m0 + 8) * 132 + k1]);
                const unsigned a2 = __float_as_uint(qs[m0 * 132 + k1 + 4]);
                const unsigned a3 = __float_as_uint(qs[(m0 + 8) * 132 + k1 + 4]);
                #pragma unroll
                for (int n = 0; n < 2; n++)
                    mma_tf32(acc[m][n][0], acc[m][n][1], acc[m][n][2], acc[m][n][3],
                             a0, a1, a2, a3, bfr[n][0], bfr[n][1]);
            }
        }
    }

    float* Sp = &g_Sp[(size_t)(bh * NCHUNK_ + chunk) * 4096];
    #pragma unroll
    for (int m = 0; m < 2; m++) {
        #pragma unroll
        for (int n = 0; n < 2; n++) {
            const int row = wm * 32 + m * 16 + lg;
            const int col = wn * 16 + n * 8 + 2 * lt;
            *(float2*)&Sp[row * 64 + col]       = make_float2(acc[m][n][0], acc[m][n][1]);
            *(float2*)&Sp[(row + 8) * 64 + col] = make_float2(acc[m][n][2], acc[m][n][3]);
        }
    }
}

// ============================================================================
// Kernel D: y = att * V via TF32 mma -> conv layout g_y[bt][oc][px].
// float4 staging; 64-reg cap for 4 blocks/SM. grid (256, 16), 256 threads.
// ============================================================================
__global__ __launch_bounds__(256, 4) void d_av_tc()
{
    extern __shared__ float sm[];
    float* as = sm;            // 64*68 = 4352
    float* vs = sm + 4352;     // 64*136 = 8704

    const int tid = threadIdx.x;
    const int dt  = blockIdx.x;
    const int bh  = blockIdx.y;
    const int d0  = dt * 128;

    for (int i = tid; i < 1024; i += 256) {     // att: 1024 float4
        const int t = i >> 4, k = (i & 15) << 2;
        const float4 a4 = *(const float4*)&g_att[(size_t)bh * 4096 + t * 64 + k];
        *(float4*)&as[t * 68 + k] = make_float4(
            to_tf32f(a4.x), to_tf32f(a4.y), to_tf32f(a4.z), to_tf32f(a4.w));
    }
    for (int i = tid; i < 2048; i += 256) {     // v: 2048 float4
        const int k = i >> 5, dd = (i & 31) << 2;
        const float4 v4 = *(const float4*)&g_v[((size_t)(bh * T_ + k)) * DD_ + d0 + dd];
        *(float4*)&vs[k * 136 + dd] = make_float4(
            to_tf32f(v4.x), to_tf32f(v4.y), to_tf32f(v4.z), to_tf32f(v4.w));
    }
    __syncthreads();

    const int warp = tid >> 5, lane = tid & 31;
    const int wm = warp & 1, wn = warp >> 1;        // wn 0..3 (d group of 32)
    const int lg = lane >> 2, lt = lane & 3;

    float acc[2][4][4];
    #pragma unroll
    for (int m = 0; m < 2; m++)
        #pragma unroll
        for (int n = 0; n < 4; n++)
            #pragma unroll
            for (int r = 0; r < 4; r++) acc[m][n][r] = 0.f;

    #pragma unroll
    for (int ks8 = 0; ks8 < 8; ks8++) {
        const int k1 = ks8 * 8 + lt;
        unsigned bfr[4][2];
        #pragma unroll
        for (int n = 0; n < 4; n++) {
            const int n0 = wn * 32 + n * 8 + lg;
            bfr[n][0] = __float_as_uint(vs[k1 * 136 + n0]);
            bfr[n][1] = __float_as_uint(vs[(k1 + 4) * 136 + n0]);
        }
        #pragma unroll
        for (int m = 0; m < 2; m++) {
            const int m0 = wm * 32 + m * 16 + lg;
            const unsigned a0 = __float_as_uint(as[m0 * 68 + k1]);
            const unsigned a1 = __float_as_uint(as[(m0 + 8) * 68 + k1]);
            const unsigned a2 = __float_as_uint(as[m0 * 68 + k1 + 4]);
            const unsigned a3 = __float_as_uint(as[(m0 + 8) * 68 + k1 + 4]);
            #pragma unroll
            for (int n = 0; n < 4; n++)
                mma_tf32(acc[m][n][0], acc[m][n][1], acc[m][n][2], acc[m][n][3],
                         a0, a1, a2, a3, bfr[n][0], bfr[n][1]);
        }
    }

    const int h = bh & 7, b = bh >> 3;
    const int hc  = d0 >> 12;
    const int px0 = d0 & 4095;
    const int oc  = h * 8 + hc;
    #pragma unroll
    for (int m = 0; m < 2; m++) {
        #pragma unroll
        for (int n = 0; n < 4; n++) {
            const int row = wm * 32 + m * 16 + lg;
            const int dcol = wn * 32 + n * 8 + 2 * lt;
            {
                const int bt = b * 64 + row;
                float* dst = &g_y[((size_t)(bt * 64 + oc)) * 4096 + px0 + dcol];
                *(float2*)dst = make_float2(acc[m][n][0], acc[m][n][1]);
            }
            {
                const int bt = b * 64 + row + 8;
                float* dst = &g_y[((size_t)(bt * 64 + oc)) * 4096 + px0 + dcol];
                *(float2*)dst = make_float2(acc[m][n][2], acc[m][n][3]);
            }
        }
    }
}

// ============================================================================
// Kernel E: reduce 32 partials + causal softmax. grid (64 t, 16 bh), 64 thr.
// ============================================================================
__global__ void e_softmax()
{
    const int t = blockIdx.x, bh = blockIdx.y, k = threadIdx.x;
    __shared__ float red[64];
    float s = 0.f;
    #pragma unroll 8
    for (int ch = 0; ch < NCHUNK_; ch++)
        s += g_Sp[((size_t)(bh * NCHUNK_ + ch) * T_ + t) * T_ + k];
    s *= 0.005524271728019903f;   // 1/sqrt(32768)
    const bool valid = (k <= t);
    red[k] = valid ? s : -3.0e38f;
    __syncthreads();
    for (int off = 32; off; off >>= 1) {
        if (k < off) red[k] = fmaxf(red[k], red[k + off]);
        __syncthreads();
    }
    const float m = red[0];
    __syncthreads();
    const float e = valid ? expf(s - m) : 0.f;
    red[k] = e;
    __syncthreads();
    for (int off = 32; off; off >>= 1) {
        if (k < off) red[k] += red[k + off];
        __syncthreads();
    }
    g_att[((size_t)bh * T_ + t) * T_ + k] = e / red[0];
}

// ============================================================================
extern "C" void kernel_launch(void* const* d_in, const int* in_sizes, int n_in,
                              void* d_out, int out_size)
{
    const float* x  = (const float*)d_in[0];
    const float* wq = (const float*)d_in[1];
    const float* bq = (const float*)d_in[2];
    const float* wk = (const float*)d_in[3];
    const float* bk = (const float*)d_in[4];
    const float* wv = (const float*)d_in[5];
    const float* bv = (const float*)d_in[6];
    const float* wo = (const float*)d_in[7];
    const float* bo = (const float*)d_in[8];
    float* out = (float*)d_out;

    const int SM1 = (14976 + XSZ_ + 96) * 4;        // 86400  -> 2 blocks/SM
    const int SM2 = (8448 + 8448) * 4;              // 67584  -> 2 blocks/SM
    const int SM4 = (4352 + 8704) * 4;              // 52224  -> 4 blocks/SM
    const int SM5 = (41472 + 2 * NX_ + 64) * 4;     // 216832 -> 1 block/SM

    cudaFuncSetAttribute(a_qkv_tc,   cudaFuncAttributeMaxDynamicSharedMemorySize, SM1);
    cudaFuncSetAttribute(c_scores_tc,cudaFuncAttributeMaxDynamicSharedMemorySize, SM2);
    cudaFuncSetAttribute(d_av_tc,    cudaFuncAttributeMaxDynamicSharedMemorySize, SM4);
    cudaFuncSetAttribute(b_convo_tc, cudaFuncAttributeMaxDynamicSharedMemorySize, SM5);

    a_qkv_tc   <<<dim3(4, 128, 2),   256, SM1>>>(x, wq, bq, wk, bk, wv, bv);
    c_scores_tc<<<dim3(NCHUNK_, 16), 256, SM2>>>();
    e_softmax  <<<dim3(64, 16),      64>>>();
    d_av_tc    <<<dim3(256, 16),     256, SM4>>>();
    b_convo_tc <<<dim3(4, 128),      256, SM5>>>(wo, bo, out);
}

// round 14
// speedup vs baseline: 1.1550x; 1.1550x over previous
#include <cuda_runtime.h>
#include <math.h>

// Problem constants
#define B_    2
#define T_    64
#define BT_   128
#define CIN_  16
#define HW_   4096
#define OC_   64
#define NH_   8
#define DD_   32768
#define BH_   16
#define NCHUNK_ 32      // score d-chunks (d=1024 each)

// ---------------- scratch (device globals) -----------------------------------
__device__ float g_q[(size_t)BH_ * T_ * DD_];            // 128 MB
__device__ float g_k[(size_t)BH_ * T_ * DD_];            // 128 MB
__device__ float g_v[(size_t)BH_ * T_ * DD_];            // 128 MB
__device__ float g_Sp[(size_t)BH_ * NCHUNK_ * T_ * T_];  // 8.4 MB
__device__ float g_att[(size_t)BH_ * T_ * T_];           // 256 KB
__device__ float g_y[(size_t)BT_ * OC_ * HW_];           // 128 MB

__device__ __forceinline__ unsigned to_tf32(float x) {
    unsigned r;
    asm("cvt.rna.tf32.f32 %0, %1;" : "=r"(r) : "f"(x));
    return r;
}
__device__ __forceinline__ float to_tf32f(float x) {
    return __uint_as_float(to_tf32(x));
}

__device__ __forceinline__ void mma_tf32(float& d0, float& d1, float& d2, float& d3,
                                         unsigned a0, unsigned a1, unsigned a2, unsigned a3,
                                         unsigned b0, unsigned b1) {
    asm volatile(
        "mma.sync.aligned.m16n8k8.row.col.f32.tf32.tf32.f32 "
        "{%0,%1,%2,%3},{%4,%5,%6,%7},{%8,%9},{%0,%1,%2,%3};"
        : "+f"(d0), "+f"(d1), "+f"(d2), "+f"(d3)
        : "r"(a0), "r"(a1), "r"(a2), "r"(a3), "r"(b0), "r"(b1));
}

// K-dimension ordering for conv GEMMs: k = r*16 + c  (r = 3x3 tap, c = channel)
// -> c = k & 15, r = k >> 4, kh = r/3 = (r*11)>>5 (exact for r<9), kw = r - 3*kh.
// x-tile channel-plane stride PSTR_=408 (== 24 mod 32): A-frag quad banks
// 24*lt + lg are full-rank -> conflict-free (396 had 2-way lt0/lt3 conflicts).
#define PSTR_ 408

// ============================================================================
// Kernel A: fused QKV 3x3 conv via TF32 tensor cores.
// M=256 (4 image rows) x 96 oc; warp tile M=64, N=48. grid (4, 128, 2);
// block loops 4 yi of 4 rows. ws[144][104]; xs[16c][plane 408] (6r x 66).
// smem 86.4 KB -> 2 blocks/SM. 8 warps: wm = warp&3 (row), wn = warp>>2.
// ============================================================================
#define WSTR_ 104
#define NXQ_ (16 * 6 * 66)   // 6336 logical staged elements
#define XSZQ_ (16 * PSTR_)   // 6528 padded region
__global__ __launch_bounds__(256, 2) void a_qkv_tc(
    const float* __restrict__ x,
    const float* __restrict__ wq, const float* __restrict__ bq,
    const float* __restrict__ wk, const float* __restrict__ bk,
    const float* __restrict__ wv, const float* __restrict__ bv)
{
    extern __shared__ float sm[];
    float* ws = sm;                  // 144*104 = 14976
    float* xs = sm + 14976;          // XSZQ_ = 6528
    float* bs = xs + XSZQ_;          // 96

    const int tid  = threadIdx.x;
    const int bt   = blockIdx.y;
    const int half = blockIdx.z;     // 0: oc 0..95, 1: oc 96..191
    const float* xin = x + (size_t)bt * CIN_ * HW_;

    // stage this half's weights once, K-reordered: ws[r*16+c][oc_l]
    {
        int oc_l = tid / 144, k = tid % 144;
        for (int idx = tid; idx < 96 * 144; idx += 256) {
            const int r = k >> 4, c = k & 15;
            const int ocg = half * 96 + oc_l;
            const float* wsrc = (ocg < 64) ? wq : ((ocg < 128) ? wk : wv);
            ws[k * WSTR_ + oc_l] = to_tf32f(wsrc[(ocg & 63) * 144 + c * 9 + r]);
            k += 112; ++oc_l;
            if (k >= 144) { k -= 144; ++oc_l; }
        }
    }
    if (tid < 96) {
        const int ocg = half * 96 + tid;
        bs[tid] = (ocg < 64) ? bq[ocg] : ((ocg < 128) ? bk[ocg - 64] : bv[ocg - 128]);
    }

    const int warp = tid >> 5, lane = tid & 31;
    const int wm = warp & 3, wn = warp >> 2;     // wm: row 0..3, wn: 0..1 (48 oc)
    const int lg = lane >> 2, lt = lane & 3;
    const int b = bt >> 6, t = bt & 63;

    // initial (c, r, cc) decomposition of tid over [16c][6r][66]
    const int c0_ = tid / 396, rem0_ = tid % 396;
    const int r0_ = rem0_ / 66, cc0_ = rem0_ % 66;

    for (int yi = 0; yi < 4; yi++) {
        const int y0 = blockIdx.x * 16 + yi * 4;   // 0..60
        __syncthreads();
        // stage x tile rows y0-1 .. y0+4 into padded layout xs[c*408 + r*66 + cc]
        {
            int c = c0_, r = r0_, cc = cc0_;
            for (int cnt = tid; cnt < NXQ_; cnt += 256) {
                const int gy = y0 - 1 + r, gx = cc - 1;
                float v = 0.f;
                if (gy >= 0 && gy < 64 && gx >= 0 && gx < 64) v = xin[c * HW_ + gy * 64 + gx];
                xs[c * PSTR_ + r * 66 + cc] = to_tf32f(v);
                cc += 58; r += 3;
                if (cc >= 66) { cc -= 66; ++r; }
                if (r >= 6)   { r -= 6;  ++c; }
            }
        }
        __syncthreads();

        float acc[4][6][4];
        #pragma unroll
        for (int m = 0; m < 4; m++)
            #pragma unroll
            for (int n = 0; n < 6; n++)
                #pragma unroll
                for (int r = 0; r < 4; r++) acc[m][n][r] = 0.f;

        #pragma unroll
        for (int kc = 0; kc < 18; kc++) {
            const int k1 = kc * 8 + lt;
            const int k2 = k1 + 4;
            const int c1 = k1 & 15, r1 = k1 >> 4;
            const int c2 = k2 & 15, r2 = k2 >> 4;
            const int t1 = (r1 * 11) >> 5;         // r1/3
            const int t2 = (r2 * 11) >> 5;
            const int aA1 = c1 * PSTR_ + (wm + t1) * 66 + (r1 - 3 * t1) + lg;
            const int aA2 = c2 * PSTR_ + (wm + t2) * 66 + (r2 - 3 * t2) + lg;

            unsigned bfr[6][2];
            #pragma unroll
            for (int n = 0; n < 6; n++) {
                const int oc_l = wn * 48 + n * 8 + lg;
                bfr[n][0] = __float_as_uint(ws[k1 * WSTR_ + oc_l]);
                bfr[n][1] = __float_as_uint(ws[k2 * WSTR_ + oc_l]);
            }
            #pragma unroll
            for (int m = 0; m < 4; m++) {
                const int xo = m * 16;
                const unsigned a0 = __float_as_uint(xs[aA1 + xo]);
                const unsigned a1 = __float_as_uint(xs[aA1 + xo + 8]);
                const unsigned a2 = __float_as_uint(xs[aA2 + xo]);
                const unsigned a3 = __float_as_uint(xs[aA2 + xo + 8]);
                #pragma unroll
                for (int n = 0; n < 6; n++)
                    mma_tf32(acc[m][n][0], acc[m][n][1], acc[m][n][2], acc[m][n][3],
                             a0, a1, a2, a3, bfr[n][0], bfr[n][1]);
            }
        }

        const int y = y0 + wm;
        #pragma unroll
        for (int m = 0; m < 4; m++) {
            #pragma unroll
            for (int n = 0; n < 6; n++) {
                const int ocA = wn * 48 + n * 8 + 2 * lt;    // local oc
                const int x0 = m * 16 + lg;
                #pragma unroll
                for (int r = 0; r < 4; r++) {
                    const int oc_l = ocA + (r & 1);
                    const int ocg  = half * 96 + oc_l;
                    const int xx = x0 + ((r & 2) ? 8 : 0);
                    float* dst = (ocg < 64) ? g_q : ((ocg < 128) ? g_k : g_v);
                    const int ol = ocg & 63;
                    const size_t addr = ((size_t)((b * 8 + (ol >> 3)) * 64 + t)) * DD_
                                      + (size_t)(ol & 7) * 4096 + y * 64 + xx;
                    dst[addr] = acc[m][n][r] + bs[oc_l];
                }
            }
        }
    }
}

// ============================================================================
// Kernel B: output 3x3 conv (64 -> 64) via TF32 tensor cores.
// Full weight panel ws[576][72] staged once; xs double-buffered (padded
// plane stride 408) with register prefetch. grid (4, 128).
// 8 warps: wm = warp&3 (row), wn = warp>>2 (oc group of 32).
// ============================================================================
#define NX_ (16 * 6 * 66)    // 6336 logical staged elements
#define XSZB_ (16 * PSTR_)   // 6528 padded region per buffer
__global__ __launch_bounds__(256) void b_convo_tc(
    const float* __restrict__ wo, const float* __restrict__ bo, float* __restrict__ out)
{
    extern __shared__ float sm[];
    float* ws = sm;                  // 576*72 = 41472
    float* xs = sm + 41472;          // 2 * 6528 = 13056
    float* bs = xs + 2 * XSZB_;      // 64

    const int tid = threadIdx.x;
    const int bt  = blockIdx.y;
    const float* yin = g_y + (size_t)bt * OC_ * HW_;

    // stage full weight panel once (incremental (oc, kg, cc2, kl) over 36864)
    {
        int oc = tid / 576, kg = tid % 576;
        int cc2 = kg / 144, kl = kg % 144;
        for (int idx = tid; idx < 64 * 576; idx += 256) {
            const int r = kl >> 4, cl = kl & 15;
            ws[kg * 72 + oc] = to_tf32f(wo[(size_t)oc * 576 + (cc2 * 16 + cl) * 9 + r]);
            kg += 256; kl += 112; cc2 += 1;
            if (kl >= 144) { kl -= 144; ++cc2; }
            if (kg >= 576) { kg -= 576; ++oc; cc2 -= 4; }
        }
    }
    if (tid < 64) bs[tid] = bo[tid];

    const int warp = tid >> 5, lane = tid & 31;
    const int wm = warp & 3, wn = warp >> 2;
    const int lg = lane >> 2, lt = lane & 3;

    // initial (c, r, cc) decomposition of tid over [16c][6r][66]
    const int c0_ = tid / 396, rem0_ = tid % 396;
    const int r0_ = rem0_ / 66, cc0_ = rem0_ % 66;

    // initial stage: s = 0 (yt=0, cc=0) into buffer 0 (padded layout)
    {
        const int y0 = blockIdx.x * 16;
        int c = c0_, r = r0_, cc = cc0_;
        for (int cnt = tid; cnt < NX_; cnt += 256) {
            const int gy = y0 - 1 + r, gx = cc - 1;
            float v = 0.f;
            if (gy >= 0 && gy < 64 && gx >= 0 && gx < 64)
                v = yin[c * HW_ + gy * 64 + gx];
            xs[c * PSTR_ + r * 66 + cc] = to_tf32f(v);
            cc += 58; r += 3;
            if (cc >= 66) { cc -= 66; ++r; }
            if (r >= 6)   { r -= 6;  ++c; }
        }
    }
    __syncthreads();

    float acc[4][4][4];

    for (int s = 0; s < 16; s++) {
        const int yt = s >> 2, cc = s & 3;
        float* xcur = xs + (s & 1) * XSZB_;
        float* xnxt = xs + ((s + 1) & 1) * XSZB_;

        float pre[25];
        if (s < 15) {
            const int s2 = s + 1;
            const int yt2 = s2 >> 2, cc2 = s2 & 3;
            const int y0n = blockIdx.x * 16 + yt2 * 4;
            int cI = c0_, rI = r0_, ccI = cc0_;
            int cnt = tid;
            #pragma unroll
            for (int j = 0; j < 25; j++) {
                float v = 0.f;
                if (cnt < NX_) {
                    const int gy = y0n - 1 + rI, gx = ccI - 1;
                    if (gy >= 0 && gy < 64 && gx >= 0 && gx < 64)
                        v = yin[(cc2 * 16 + cI) * HW_ + gy * 64 + gx];
                }
                pre[j] = v;
                cnt += 256;
                ccI += 58; rI += 3;
                if (ccI >= 66) { ccI -= 66; ++rI; }
                if (rI >= 6)   { rI -= 6;  ++cI; }
            }
        }

        if (cc == 0) {
            #pragma unroll
            for (int m = 0; m < 4; m++)
                #pragma unroll
                for (int n = 0; n < 4; n++)
                    #pragma unroll
                    for (int r = 0; r < 4; r++) acc[m][n][r] = 0.f;
        }

        #pragma unroll
        for (int kc = 0; kc < 18; kc++) {
            const int k1 = kc * 8 + lt;
            const int k2 = k1 + 4;
            const int c1 = k1 & 15, r1 = k1 >> 4;
            const int c2 = k2 & 15, r2 = k2 >> 4;
            const int t1 = (r1 * 11) >> 5;         // r1/3
            const int t2 = (r2 * 11) >> 5;
            const int aA1 = c1 * PSTR_ + (wm + t1) * 66 + (r1 - 3 * t1) + lg;
            const int aA2 = c2 * PSTR_ + (wm + t2) * 66 + (r2 - 3 * t2) + lg;
            const int kg1 = cc * 144 + k1, kg2 = cc * 144 + k2;

            unsigned bfr[4][2];
            #pragma unroll
            for (int n = 0; n < 4; n++) {
                const int oc = wn * 32 + n * 8 + lg;
                bfr[n][0] = __float_as_uint(ws[kg1 * 72 + oc]);
                bfr[n][1] = __float_as_uint(ws[kg2 * 72 + oc]);
            }
            #pragma unroll
            for (int m = 0; m < 4; m++) {
                const int xo = m * 16;
                const unsigned a0 = __float_as_uint(xcur[aA1 + xo]);
                const unsigned a1 = __float_as_uint(xcur[aA1 + xo + 8]);
                const unsigned a2 = __float_as_uint(xcur[aA2 + xo]);
                const unsigned a3 = __float_as_uint(xcur[aA2 + xo + 8]);
                #pragma unroll
                for (int n = 0; n < 4; n++)
                    mma_tf32(acc[m][n][0], acc[m][n][1], acc[m][n][2], acc[m][n][3],
                             a0, a1, a2, a3, bfr[n][0], bfr[n][1]);
            }
        }

        // commit prefetched tile to the other buffer (same carry walk)
        if (s < 15) {
            int cI = c0_, rI = r0_, ccI = cc0_;
            int cnt = tid;
            #pragma unroll
            for (int j = 0; j < 25; j++) {
                if (cnt < NX_) xnxt[cI * PSTR_ + rI * 66 + ccI] = to_tf32f(pre[j]);
                cnt += 256;
                ccI += 58; rI += 3;
                if (ccI >= 66) { ccI -= 66; ++rI; }
                if (rI >= 6)   { rI -= 6;  ++cI; }
            }
        }
        __syncthreads();

        if (cc == 3) {
            const int y = blockIdx.x * 16 + yt * 4 + wm;
            #pragma unroll
            for (int m = 0; m < 4; m++) {
                #pragma unroll
                for (int n = 0; n < 4; n++) {
                    const int ocA = wn * 32 + n * 8 + 2 * lt;
                    const int x0 = m * 16 + lg;
                    #pragma unroll
                    for (int r = 0; r < 4; r++) {
                        const int oc = ocA + (r & 1);
                        const int xx = x0 + ((r & 2) ? 8 : 0);
                        out[((size_t)(bt * 64 + oc)) * 4096 + y * 64 + xx] = acc[m][n][r] + bs[oc];
                    }
                }
            }
        }
    }
}

// ============================================================================
// Kernel C: partial scores via TF32 mma. Sp[bh][chunk][64][64], d-chunk 1024.
// Natural [row][dd] stride-132 staging, float4 coalesced, conflict-free.
// smem 67.6 KB -> 2 blocks/SM. grid (32, 16), 256 threads.
// ============================================================================
__global__ __launch_bounds__(256, 2) void c_scores_tc()
{
    extern __shared__ float sm[];
    float* qs = sm;            // 64*132 = 8448
    float* kn = sm + 8448;     // 64*132 = 8448

    const int tid   = threadIdx.x;
    const int chunk = blockIdx.x;   // 0..31
    const int bh    = blockIdx.y;
    const int warp = tid >> 5, lane = tid & 31;
    const int wm = warp & 1, wn = warp >> 1;        // wn 0..3
    const int lg = lane >> 2, lt = lane & 3;

    float acc[2][2][4];
    #pragma unroll
    for (int m = 0; m < 2; m++)
        #pragma unroll
        for (int n = 0; n < 2; n++)
            #pragma unroll
            for (int r = 0; r < 4; r++) acc[m][n][r] = 0.f;

    for (int sub = 0; sub < 8; sub++) {
        const int d0 = chunk * 1024 + sub * 128;
        __syncthreads();
        for (int i = tid; i < 2048; i += 256) {      // float4 granularity
            const int row = i >> 5, dd = (i & 31) << 2;
            const size_t g = ((size_t)(bh * T_ + row)) * DD_ + d0 + dd;
            const float4 q4 = *(const float4*)&g_q[g];
            const float4 k4 = *(const float4*)&g_k[g];
            *(float4*)&qs[row * 132 + dd] = make_float4(
                to_tf32f(q4.x), to_tf32f(q4.y), to_tf32f(q4.z), to_tf32f(q4.w));
            *(float4*)&kn[row * 132 + dd] = make_float4(
                to_tf32f(k4.x), to_tf32f(k4.y), to_tf32f(k4.z), to_tf32f(k4.w));
        }
        __syncthreads();

        #pragma unroll
        for (int ks8 = 0; ks8 < 16; ks8++) {
            const int k1 = ks8 * 8 + lt;
            unsigned bfr[2][2];
            #pragma unroll
            for (int n = 0; n < 2; n++) {
                const int n0 = wn * 16 + n * 8 + lg;
                bfr[n][0] = __float_as_uint(kn[n0 * 132 + k1]);
                bfr[n][1] = __float_as_uint(kn[n0 * 132 + k1 + 4]);
            }
            #pragma unroll
            for (int m = 0; m < 2; m++) {
                const int m0 = wm * 32 + m * 16 + lg;
                const unsigned a0 = __float_as_uint(qs[m0 * 132 + k1]);
                const unsigned a1 = __float_as_uint(qs[(m0 + 8) * 132 + k1]);
                const unsigned a2 = __float_as_uint(qs[m0 * 132 + k1 + 4]);
                const unsigned a3 = __float_as_uint(qs[(m0 + 8) * 132 + k1 + 4]);
                #pragma unroll
                for (int n = 0; n < 2; n++)
                    mma_tf32(acc[m][n][0], acc[m][n][1], acc[m][n][2], acc[m][n][3],
                             a0, a1, a2, a3, bfr[n][0], bfr[n][1]);
            }
        }
    }

    float* Sp = &g_Sp[(size_t)(bh * NCHUNK_ + chunk) * 4096];
    #pragma unroll
    for (int m = 0; m < 2; m++) {
        #pragma unroll
        for (int n = 0; n < 2; n++) {
            const int row = wm * 32 + m * 16 + lg;
            const int col = wn * 16 + n * 8 + 2 * lt;
            *(float2*)&Sp[row * 64 + col]       = make_float2(acc[m][n][0], acc[m][n][1]);
            *(float2*)&Sp[(row + 8) * 64 + col] = make_float2(acc[m][n][2], acc[m][n][3]);
        }
    }
}

// ============================================================================
// Kernel D: y = att * V via TF32 mma -> conv layout g_y[bt][oc][px].
// float4 staging; 64-reg cap for 4 blocks/SM. grid (256, 16), 256 threads.
// ============================================================================
__global__ __launch_bounds__(256, 4) void d_av_tc()
{
    extern __shared__ float sm[];
    float* as = sm;            // 64*68 = 4352
    float* vs = sm + 4352;     // 64*136 = 8704

    const int tid = threadIdx.x;
    const int dt  = blockIdx.x;
    const int bh  = blockIdx.y;
    const int d0  = dt * 128;

    for (int i = tid; i < 1024; i += 256) {     // att: 1024 float4
        const int t = i >> 4, k = (i & 15) << 2;
        const float4 a4 = *(const float4*)&g_att[(size_t)bh * 4096 + t * 64 + k];
        *(float4*)&as[t * 68 + k] = make_float4(
            to_tf32f(a4.x), to_tf32f(a4.y), to_tf32f(a4.z), to_tf32f(a4.w));
    }
    for (int i = tid; i < 2048; i += 256) {     // v: 2048 float4
        const int k = i >> 5, dd = (i & 31) << 2;
        const float4 v4 = *(const float4*)&g_v[((size_t)(bh * T_ + k)) * DD_ + d0 + dd];
        *(float4*)&vs[k * 136 + dd] = make_float4(
            to_tf32f(v4.x), to_tf32f(v4.y), to_tf32f(v4.z), to_tf32f(v4.w));
    }
    __syncthreads();

    const int warp = tid >> 5, lane = tid & 31;
    const int wm = warp & 1, wn = warp >> 1;        // wn 0..3 (d group of 32)
    const int lg = lane >> 2, lt = lane & 3;

    float acc[2][4][4];
    #pragma unroll
    for (int m = 0; m < 2; m++)
        #pragma unroll
        for (int n = 0; n < 4; n++)
            #pragma unroll
            for (int r = 0; r < 4; r++) acc[m][n][r] = 0.f;

    #pragma unroll
    for (int ks8 = 0; ks8 < 8; ks8++) {
        const int k1 = ks8 * 8 + lt;
        unsigned bfr[4][2];
        #pragma unroll
        for (int n = 0; n < 4; n++) {
            const int n0 = wn * 32 + n * 8 + lg;
            bfr[n][0] = __float_as_uint(vs[k1 * 136 + n0]);
            bfr[n][1] = __float_as_uint(vs[(k1 + 4) * 136 + n0]);
        }
        #pragma unroll
        for (int m = 0; m < 2; m++) {
            const int m0 = wm * 32 + m * 16 + lg;
            const unsigned a0 = __float_as_uint(as[m0 * 68 + k1]);
            const unsigned a1 = __float_as_uint(as[(m0 + 8) * 68 + k1]);
            const unsigned a2 = __float_as_uint(as[m0 * 68 + k1 + 4]);
            const unsigned a3 = __float_as_uint(as[(m0 + 8) * 68 + k1 + 4]);
            #pragma unroll
            for (int n = 0; n < 4; n++)
                mma_tf32(acc[m][n][0], acc[m][n][1], acc[m][n][2], acc[m][n][3],
                         a0, a1, a2, a3, bfr[n][0], bfr[n][1]);
        }
    }

    const int h = bh & 7, b = bh >> 3;
    const int hc  = d0 >> 12;
    const int px0 = d0 & 4095;
    const int oc  = h * 8 + hc;
    #pragma unroll
    for (int m = 0; m < 2; m++) {
        #pragma unroll
        for (int n = 0; n < 4; n++) {
            const int row = wm * 32 + m * 16 + lg;
            const int dcol = wn * 32 + n * 8 + 2 * lt;
            {
                const int bt = b * 64 + row;
                float* dst = &g_y[((size_t)(bt * 64 + oc)) * 4096 + px0 + dcol];
                *(float2*)dst = make_float2(acc[m][n][0], acc[m][n][1]);
            }
            {
                const int bt = b * 64 + row + 8;
                float* dst = &g_y[((size_t)(bt * 64 + oc)) * 4096 + px0 + dcol];
                *(float2*)dst = make_float2(acc[m][n][2], acc[m][n][3]);
            }
        }
    }
}

// ============================================================================
// Kernel E: reduce 32 partials + causal softmax. grid (64 t, 16 bh), 64 thr.
// ============================================================================
__global__ void e_softmax()
{
    const int t = blockIdx.x, bh = blockIdx.y, k = threadIdx.x;
    __shared__ float red[64];
    float s = 0.f;
    #pragma unroll 8
    for (int ch = 0; ch < NCHUNK_; ch++)
        s += g_Sp[((size_t)(bh * NCHUNK_ + ch) * T_ + t) * T_ + k];
    s *= 0.005524271728019903f;   // 1/sqrt(32768)
    const bool valid = (k <= t);
    red[k] = valid ? s : -3.0e38f;
    __syncthreads();
    for (int off = 32; off; off >>= 1) {
        if (k < off) red[k] = fmaxf(red[k], red[k + off]);
        __syncthreads();
    }
    const float m = red[0];
    __syncthreads();
    const float e = valid ? expf(s - m) : 0.f;
    red[k] = e;
    __syncthreads();
    for (int off = 32; off; off >>= 1) {
        if (k < off) red[k] += red[k + off];
        __syncthreads();
    }
    g_att[((size_t)bh * T_ + t) * T_ + k] = e / red[0];
}

// ============================================================================
extern "C" void kernel_launch(void* const* d_in, const int* in_sizes, int n_in,
                              void* d_out, int out_size)
{
    const float* x  = (const float*)d_in[0];
    const float* wq = (const float*)d_in[1];
    const float* bq = (const float*)d_in[2];
    const float* wk = (const float*)d_in[3];
    const float* bk = (const float*)d_in[4];
    const float* wv = (const float*)d_in[5];
    const float* bv = (const float*)d_in[6];
    const float* wo = (const float*)d_in[7];
    const float* bo = (const float*)d_in[8];
    float* out = (float*)d_out;

    const int SM1 = (14976 + XSZQ_ + 96) * 4;       // 86400  -> 2 blocks/SM
    const int SM2 = (8448 + 8448) * 4;              // 67584  -> 2 blocks/SM
    const int SM4 = (4352 + 8704) * 4;              // 52224  -> 4 blocks/SM
    const int SM5 = (41472 + 2 * XSZB_ + 64) * 4;   // 218368 -> 1 block/SM

    cudaFuncSetAttribute(a_qkv_tc,   cudaFuncAttributeMaxDynamicSharedMemorySize, SM1);
    cudaFuncSetAttribute(c_scores_tc,cudaFuncAttributeMaxDynamicSharedMemorySize, SM2);
    cudaFuncSetAttribute(d_av_tc,    cudaFuncAttributeMaxDynamicSharedMemorySize, SM4);
    cudaFuncSetAttribute(b_convo_tc, cudaFuncAttributeMaxDynamicSharedMemorySize, SM5);

    a_qkv_tc   <<<dim3(4, 128, 2),   256, SM1>>>(x, wq, bq, wk, bk, wv, bv);
    c_scores_tc<<<dim3(NCHUNK_, 16), 256, SM2>>>();
    e_softmax  <<<dim3(64, 16),      64>>>();
    d_av_tc    <<<dim3(256, 16),     256, SM4>>>();
    b_convo_tc <<<dim3(4, 128),      256, SM5>>>(wo, bo, out);
}

// round 16
// speedup vs baseline: 1.2062x; 1.0443x over previous
#include <cuda_runtime.h>
#include <math.h>

// Problem constants
#define B_    2
#define T_    64
#define BT_   128
#define CIN_  16
#define HW_   4096
#define OC_   64
#define NH_   8
#define DD_   32768
#define BH_   16
#define NCHUNK_ 32      // score d-chunks (d=1024 each)

// ---------------- scratch (device globals) -----------------------------------
// NOTE: q/k/v/att/y are stored ALREADY tf32-rounded (producers apply rna at the
// write; rna is idempotent, so consumer-side re-rounding is a no-op and the
// scores/av staging paths copy raw bits via cp.async).
__device__ float g_q[(size_t)BH_ * T_ * DD_];            // 128 MB
__device__ float g_k[(size_t)BH_ * T_ * DD_];            // 128 MB
__device__ float g_v[(size_t)BH_ * T_ * DD_];            // 128 MB
__device__ float g_Sp[(size_t)BH_ * NCHUNK_ * T_ * T_];  // 8.4 MB
__device__ float g_att[(size_t)BH_ * T_ * T_];           // 256 KB
__device__ float g_y[(size_t)BT_ * OC_ * HW_];           // 128 MB

__device__ __forceinline__ unsigned to_tf32(float x) {
    unsigned r;
    asm("cvt.rna.tf32.f32 %0, %1;" : "=r"(r) : "f"(x));
    return r;
}
__device__ __forceinline__ float to_tf32f(float x) {
    return __uint_as_float(to_tf32(x));
}

__device__ __forceinline__ unsigned s2u(const void* p) {
    unsigned a;
    asm("{ .reg .u64 t; cvta.to.shared.u64 t, %1; cvt.u32.u64 %0, t; }"
        : "=r"(a) : "l"(p));
    return a;
}
#define CP16(dst_u32, src_ptr) \
    asm volatile("cp.async.cg.shared.global [%0], [%1], 16;" \
                 :: "r"(dst_u32), "l"(src_ptr))
#define CP_COMMIT()  asm volatile("cp.async.commit_group;" ::: "memory")
#define CP_WAIT0()   asm volatile("cp.async.wait_group 0;" ::: "memory")

__device__ __forceinline__ void mma_tf32(float& d0, float& d1, float& d2, float& d3,
                                         unsigned a0, unsigned a1, unsigned a2, unsigned a3,
                                         unsigned b0, unsigned b1) {
    asm volatile(
        "mma.sync.aligned.m16n8k8.row.col.f32.tf32.tf32.f32 "
        "{%0,%1,%2,%3},{%4,%5,%6,%7},{%8,%9},{%0,%1,%2,%3};"
        : "+f"(d0), "+f"(d1), "+f"(d2), "+f"(d3)
        : "r"(a0), "r"(a1), "r"(a2), "r"(a3), "r"(b0), "r"(b1));
}

// K-dimension ordering for conv GEMMs: k = r*16 + c  (r = 3x3 tap, c = channel)
// -> c = k & 15, r = k >> 4, kh = r/3 = (r*11)>>5 (exact for r<9), kw = r - 3*kh.
// x-tile channel-plane stride PSTR_=408 (== 24 mod 32): A-frag quad banks
// 24*lt + lg full-rank -> conflict-free.
#define PSTR_ 408

// ============================================================================
// Kernel A: fused QKV 3x3 conv via TF32 tensor cores.
// M=256 (4 image rows) x 96 oc; warp tile M=64, N=48. grid (4, 128, 2);
// block loops 4 yi of 4 rows. ws[144][104]; xs[16c][plane 408].
// Epilogue writes tf32-rounded values (producer-side rna).
// smem 86.4 KB -> 2 blocks/SM. 8 warps: wm = warp&3 (row), wn = warp>>2.
// ============================================================================
#define WSTR_ 104
#define NXQ_ (16 * 6 * 66)   // 6336 logical staged elements
#define XSZQ_ (16 * PSTR_)   // 6528 padded region
__global__ __launch_bounds__(256, 2) void a_qkv_tc(
    const float* __restrict__ x,
    const float* __restrict__ wq, const float* __restrict__ bq,
    const float* __restrict__ wk, const float* __restrict__ bk,
    const float* __restrict__ wv, const float* __restrict__ bv)
{
    extern __shared__ float sm[];
    float* ws = sm;                  // 144*104 = 14976
    float* xs = sm + 14976;          // XSZQ_ = 6528
    float* bs = xs + XSZQ_;          // 96

    const int tid  = threadIdx.x;
    const int bt   = blockIdx.y;
    const int half = blockIdx.z;     // 0: oc 0..95, 1: oc 96..191
    const float* xin = x + (size_t)bt * CIN_ * HW_;

    // stage this half's weights once, K-reordered: ws[r*16+c][oc_l]
    {
        int oc_l = tid / 144, k = tid % 144;
        for (int idx = tid; idx < 96 * 144; idx += 256) {
            const int r = k >> 4, c = k & 15;
            const int ocg = half * 96 + oc_l;
            const float* wsrc = (ocg < 64) ? wq : ((ocg < 128) ? wk : wv);
            ws[k * WSTR_ + oc_l] = to_tf32f(wsrc[(ocg & 63) * 144 + c * 9 + r]);
            k += 112; ++oc_l;
            if (k >= 144) { k -= 144; ++oc_l; }
        }
    }
    if (tid < 96) {
        const int ocg = half * 96 + tid;
        bs[tid] = (ocg < 64) ? bq[ocg] : ((ocg < 128) ? bk[ocg - 64] : bv[ocg - 128]);
    }

    const int warp = tid >> 5, lane = tid & 31;
    const int wm = warp & 3, wn = warp >> 2;     // wm: row 0..3, wn: 0..1 (48 oc)
    const int lg = lane >> 2, lt = lane & 3;
    const int b = bt >> 6, t = bt & 63;

    // initial (c, r, cc) decomposition of tid over [16c][6r][66]
    const int c0_ = tid / 396, rem0_ = tid % 396;
    const int r0_ = rem0_ / 66, cc0_ = rem0_ % 66;

    for (int yi = 0; yi < 4; yi++) {
        const int y0 = blockIdx.x * 16 + yi * 4;   // 0..60
        __syncthreads();
        // stage x tile rows y0-1 .. y0+4 into padded layout xs[c*408 + r*66 + cc]
        {
            int c = c0_, r = r0_, cc = cc0_;
            for (int cnt = tid; cnt < NXQ_; cnt += 256) {
                const int gy = y0 - 1 + r, gx = cc - 1;
                float v = 0.f;
                if (gy >= 0 && gy < 64 && gx >= 0 && gx < 64) v = xin[c * HW_ + gy * 64 + gx];
                xs[c * PSTR_ + r * 66 + cc] = to_tf32f(v);
                cc += 58; r += 3;
                if (cc >= 66) { cc -= 66; ++r; }
                if (r >= 6)   { r -= 6;  ++c; }
            }
        }
        __syncthreads();

        float acc[4][6][4];
        #pragma unroll
        for (int m = 0; m < 4; m++)
            #pragma unroll
            for (int n = 0; n < 6; n++)
                #pragma unroll
                for (int r = 0; r < 4; r++) acc[m][n][r] = 0.f;

        #pragma unroll
        for (int kc = 0; kc < 18; kc++) {
            const int k1 = kc * 8 + lt;
            const int k2 = k1 + 4;
            const int c1 = k1 & 15, r1 = k1 >> 4;
            const int c2 = k2 & 15, r2 = k2 >> 4;
            const int t1 = (r1 * 11) >> 5;         // r1/3
            const int t2 = (r2 * 11) >> 5;
            const int aA1 = c1 * PSTR_ + (wm + t1) * 66 + (r1 - 3 * t1) + lg;
            const int aA2 = c2 * PSTR_ + (wm + t2) * 66 + (r2 - 3 * t2) + lg;

            unsigned bfr[6][2];
            #pragma unroll
            for (int n = 0; n < 6; n++) {
                const int oc_l = wn * 48 + n * 8 + lg;
                bfr[n][0] = __float_as_uint(ws[k1 * WSTR_ + oc_l]);
                bfr[n][1] = __float_as_uint(ws[k2 * WSTR_ + oc_l]);
            }
            #pragma unroll
            for (int m = 0; m < 4; m++) {
                const int xo = m * 16;
                const unsigned a0 = __float_as_uint(xs[aA1 + xo]);
                const unsigned a1 = __float_as_uint(xs[aA1 + xo + 8]);
                const unsigned a2 = __float_as_uint(xs[aA2 + xo]);
                const unsigned a3 = __float_as_uint(xs[aA2 + xo + 8]);
                #pragma unroll
                for (int n = 0; n < 6; n++)
                    mma_tf32(acc[m][n][0], acc[m][n][1], acc[m][n][2], acc[m][n][3],
                             a0, a1, a2, a3, bfr[n][0], bfr[n][1]);
            }
        }

        const int y = y0 + wm;
        #pragma unroll
        for (int m = 0; m < 4; m++) {
            #pragma unroll
            for (int n = 0; n < 6; n++) {
                const int ocA = wn * 48 + n * 8 + 2 * lt;    // local oc
                const int x0 = m * 16 + lg;
                #pragma unroll
                for (int r = 0; r < 4; r++) {
                    const int oc_l = ocA + (r & 1);
                    const int ocg  = half * 96 + oc_l;
                    const int xx = x0 + ((r & 2) ? 8 : 0);
                    float* dst = (ocg < 64) ? g_q : ((ocg < 128) ? g_k : g_v);
                    const int ol = ocg & 63;
                    const size_t addr = ((size_t)((b * 8 + (ol >> 3)) * 64 + t)) * DD_
                                      + (size_t)(ol & 7) * 4096 + y * 64 + xx;
                    dst[addr] = to_tf32f(acc[m][n][r] + bs[oc_l]);   // producer-side rna
                }
            }
        }
    }
}

// ============================================================================
// Kernel B: output 3x3 conv (64 -> 64) via TF32 tensor cores.
// Full weight panel ws[576][72] staged once; xs double-buffered (padded
// plane stride 408) with register prefetch. grid (4, 128).
// (y is already tf32; staging cvt is idempotent and kept.)
// ============================================================================
#define NX_ (16 * 6 * 66)    // 6336 logical staged elements
#define XSZB_ (16 * PSTR_)   // 6528 padded region per buffer
__global__ __launch_bounds__(256) void b_convo_tc(
    const float* __restrict__ wo, const float* __restrict__ bo, float* __restrict__ out)
{
    extern __shared__ float sm[];
    float* ws = sm;                  // 576*72 = 41472
    float* xs = sm + 41472;          // 2 * 6528 = 13056
    float* bs = xs + 2 * XSZB_;      // 64

    const int tid = threadIdx.x;
    const int bt  = blockIdx.y;
    const float* yin = g_y + (size_t)bt * OC_ * HW_;

    // stage full weight panel once (incremental (oc, kg, cc2, kl) over 36864)
    {
        int oc = tid / 576, kg = tid % 576;
        int cc2 = kg / 144, kl = kg % 144;
        for (int idx = tid; idx < 64 * 576; idx += 256) {
            const int r = kl >> 4, cl = kl & 15;
            ws[kg * 72 + oc] = to_tf32f(wo[(size_t)oc * 576 + (cc2 * 16 + cl) * 9 + r]);
            kg += 256; kl += 112; cc2 += 1;
            if (kl >= 144) { kl -= 144; ++cc2; }
            if (kg >= 576) { kg -= 576; ++oc; cc2 -= 4; }
        }
    }
    if (tid < 64) bs[tid] = bo[tid];

    const int warp = tid >> 5, lane = tid & 31;
    const int wm = warp & 3, wn = warp >> 2;
    const int lg = lane >> 2, lt = lane & 3;

    // initial (c, r, cc) decomposition of tid over [16c][6r][66]
    const int c0_ = tid / 396, rem0_ = tid % 396;
    const int r0_ = rem0_ / 66, cc0_ = rem0_ % 66;

    // initial stage: s = 0 into buffer 0 (padded layout)
    {
        const int y0 = blockIdx.x * 16;
        int c = c0_, r = r0_, cc = cc0_;
        for (int cnt = tid; cnt < NX_; cnt += 256) {
            const int gy = y0 - 1 + r, gx = cc - 1;
            float v = 0.f;
            if (gy >= 0 && gy < 64 && gx >= 0 && gx < 64)
                v = yin[c * HW_ + gy * 64 + gx];
            xs[c * PSTR_ + r * 66 + cc] = to_tf32f(v);
            cc += 58; r += 3;
            if (cc >= 66) { cc -= 66; ++r; }
            if (r >= 6)   { r -= 6;  ++c; }
        }
    }
    __syncthreads();

    float acc[4][4][4];

    for (int s = 0; s < 16; s++) {
        const int yt = s >> 2, cc = s & 3;
        float* xcur = xs + (s & 1) * XSZB_;
        float* xnxt = xs + ((s + 1) & 1) * XSZB_;

        float pre[25];
        if (s < 15) {
            const int s2 = s + 1;
            const int yt2 = s2 >> 2, cc2 = s2 & 3;
            const int y0n = blockIdx.x * 16 + yt2 * 4;
            int cI = c0_, rI = r0_, ccI = cc0_;
            int cnt = tid;
            #pragma unroll
            for (int j = 0; j < 25; j++) {
                float v = 0.f;
                if (cnt < NX_) {
                    const int gy = y0n - 1 + rI, gx = ccI - 1;
                    if (gy >= 0 && gy < 64 && gx >= 0 && gx < 64)
                        v = yin[(cc2 * 16 + cI) * HW_ + gy * 64 + gx];
                }
                pre[j] = v;
                cnt += 256;
                ccI += 58; rI += 3;
                if (ccI >= 66) { ccI -= 66; ++rI; }
                if (rI >= 6)   { rI -= 6;  ++cI; }
            }
        }

        if (cc == 0) {
            #pragma unroll
            for (int m = 0; m < 4; m++)
                #pragma unroll
                for (int n = 0; n < 4; n++)
                    #pragma unroll
                    for (int r = 0; r < 4; r++) acc[m][n][r] = 0.f;
        }

        #pragma unroll
        for (int kc = 0; kc < 18; kc++) {
            const int k1 = kc * 8 + lt;
            const int k2 = k1 + 4;
            const int c1 = k1 & 15, r1 = k1 >> 4;
            const int c2 = k2 & 15, r2 = k2 >> 4;
            const int t1 = (r1 * 11) >> 5;         // r1/3
            const int t2 = (r2 * 11) >> 5;
            const int aA1 = c1 * PSTR_ + (wm + t1) * 66 + (r1 - 3 * t1) + lg;
            const int aA2 = c2 * PSTR_ + (wm + t2) * 66 + (r2 - 3 * t2) + lg;
            const int kg1 = cc * 144 + k1, kg2 = cc * 144 + k2;

            unsigned bfr[4][2];
            #pragma unroll
            for (int n = 0; n < 4; n++) {
                const int oc = wn * 32 + n * 8 + lg;
                bfr[n][0] = __float_as_uint(ws[kg1 * 72 + oc]);
                bfr[n][1] = __float_as_uint(ws[kg2 * 72 + oc]);
            }
            #pragma unroll
            for (int m = 0; m < 4; m++) {
                const int xo = m * 16;
                const unsigned a0 = __float_as_uint(xcur[aA1 + xo]);
                const unsigned a1 = __float_as_uint(xcur[aA1 + xo + 8]);
                const unsigned a2 = __float_as_uint(xcur[aA2 + xo]);
                const unsigned a3 = __float_as_uint(xcur[aA2 + xo + 8]);
                #pragma unroll
                for (int n = 0; n < 4; n++)
                    mma_tf32(acc[m][n][0], acc[m][n][1], acc[m][n][2], acc[m][n][3],
                             a0, a1, a2, a3, bfr[n][0], bfr[n][1]);
            }
        }

        // commit prefetched tile to the other buffer (same carry walk)
        if (s < 15) {
            int cI = c0_, rI = r0_, ccI = cc0_;
            int cnt = tid;
            #pragma unroll
            for (int j = 0; j < 25; j++) {
                if (cnt < NX_) xnxt[cI * PSTR_ + rI * 66 + ccI] = to_tf32f(pre[j]);
                cnt += 256;
                ccI += 58; rI += 3;
                if (ccI >= 66) { ccI -= 66; ++rI; }
                if (rI >= 6)   { rI -= 6;  ++cI; }
            }
        }
        __syncthreads();

        if (cc == 3) {
            const int y = blockIdx.x * 16 + yt * 4 + wm;
            #pragma unroll
            for (int m = 0; m < 4; m++) {
                #pragma unroll
                for (int n = 0; n < 4; n++) {
                    const int ocA = wn * 32 + n * 8 + 2 * lt;
                    const int x0 = m * 16 + lg;
                    #pragma unroll
                    for (int r = 0; r < 4; r++) {
                        const int oc = ocA + (r & 1);
                        const int xx = x0 + ((r & 2) ? 8 : 0);
                        out[((size_t)(bt * 64 + oc)) * 4096 + y * 64 + xx] = acc[m][n][r] + bs[oc];
                    }
                }
            }
        }
    }
}

// ============================================================================
// Kernel C: partial scores via TF32 mma. Sp[bh][chunk][64][64], d-chunk 1024.
// q/k are tf32 in HBM -> staging is raw cp.async 16B (no cvt, no reg traffic).
// smem 67.6 KB -> 2 blocks/SM. grid (32, 16), 256 threads.
// ============================================================================
__global__ __launch_bounds__(256, 2) void c_scores_tc()
{
    extern __shared__ float sm[];
    float* qs = sm;            // 64*132 = 8448
    float* kn = sm + 8448;     // 64*132 = 8448

    const int tid   = threadIdx.x;
    const int chunk = blockIdx.x;   // 0..31
    const int bh    = blockIdx.y;
    const int warp = tid >> 5, lane = tid & 31;
    const int wm = warp & 1, wn = warp >> 1;        // wn 0..3
    const int lg = lane >> 2, lt = lane & 3;

    float acc[2][2][4];
    #pragma unroll
    for (int m = 0; m < 2; m++)
        #pragma unroll
        for (int n = 0; n < 2; n++)
            #pragma unroll
            for (int r = 0; r < 4; r++) acc[m][n][r] = 0.f;

    for (int sub = 0; sub < 8; sub++) {
        const int d0 = chunk * 1024 + sub * 128;
        __syncthreads();
        #pragma unroll
        for (int i = tid; i < 2048; i += 256) {      // float4 granularity
            const int row = i >> 5, dd = (i & 31) << 2;
            const size_t g = ((size_t)(bh * T_ + row)) * DD_ + d0 + dd;
            CP16(s2u(&qs[row * 132 + dd]), &g_q[g]);
            CP16(s2u(&kn[row * 132 + dd]), &g_k[g]);
        }
        CP_COMMIT();
        CP_WAIT0();
        __syncthreads();

        #pragma unroll
        for (int ks8 = 0; ks8 < 16; ks8++) {
            const int k1 = ks8 * 8 + lt;
            unsigned bfr[2][2];
            #pragma unroll
            for (int n = 0; n < 2; n++) {
                const int n0 = wn * 16 + n * 8 + lg;
                bfr[n][0] = __float_as_uint(kn[n0 * 132 + k1]);
                bfr[n][1] = __float_as_uint(kn[n0 * 132 + k1 + 4]);
            }
            #pragma unroll
            for (int m = 0; m < 2; m++) {
                const int m0 = wm * 32 + m * 16 + lg;
                const unsigned a0 = __float_as_uint(qs[m0 * 132 + k1]);
                const unsigned a1 = __float_as_uint(qs[(m0 + 8) * 132 + k1]);
                const unsigned a2 = __float_as_uint(qs[m0 * 132 + k1 + 4]);
                const unsigned a3 = __float_as_uint(qs[(m0 + 8) * 132 + k1 + 4]);
                #pragma unroll
                for (int n = 0; n < 2; n++)
                    mma_tf32(acc[m][n][0], acc[m][n][1], acc[m][n][2], acc[m][n][3],
                             a0, a1, a2, a3, bfr[n][0], bfr[n][1]);
            }
        }
    }

    float* Sp = &g_Sp[(size_t)(bh * NCHUNK_ + chunk) * 4096];
    #pragma unroll
    for (int m = 0; m < 2; m++) {
        #pragma unroll
        for (int n = 0; n < 2; n++) {
            const int row = wm * 32 + m * 16 + lg;
            const int col = wn * 16 + n * 8 + 2 * lt;
            *(float2*)&Sp[row * 64 + col]       = make_float2(acc[m][n][0], acc[m][n][1]);
            *(float2*)&Sp[(row + 8) * 64 + col] = make_float2(acc[m][n][2], acc[m][n][3]);
        }
    }
}

// ============================================================================
// Kernel D: y = att * V via TF32 mma -> conv layout g_y[bt][oc][px].
// att/v are tf32 in HBM -> raw cp.async 16B staging. y written tf32-rounded.
// 64-reg cap, 4 blocks/SM. grid (256, 16), 256 threads.
// ============================================================================
__global__ __launch_bounds__(256, 4) void d_av_tc()
{
    extern __shared__ float sm[];
    float* as = sm;            // 64*68 = 4352
    float* vs = sm + 4352;     // 64*136 = 8704

    const int tid = threadIdx.x;
    const int dt  = blockIdx.x;
    const int bh  = blockIdx.y;
    const int d0  = dt * 128;

    #pragma unroll
    for (int i = tid; i < 1024; i += 256) {     // att: 1024 float4
        const int t = i >> 4, k = (i & 15) << 2;
        CP16(s2u(&as[t * 68 + k]), &g_att[(size_t)bh * 4096 + t * 64 + k]);
    }
    #pragma unroll
    for (int i = tid; i < 2048; i += 256) {     // v: 2048 float4
        const int k = i >> 5, dd = (i & 31) << 2;
        CP16(s2u(&vs[k * 136 + dd]), &g_v[((size_t)(bh * T_ + k)) * DD_ + d0 + dd]);
    }
    CP_COMMIT();
    CP_WAIT0();
    __syncthreads();

    const int warp = tid >> 5, lane = tid & 31;
    const int wm = warp & 1, wn = warp >> 1;        // wn 0..3 (d group of 32)
    const int lg = lane >> 2, lt = lane & 3;

    float acc[2][4][4];
    #pragma unroll
    for (int m = 0; m < 2; m++)
        #pragma unroll
        for (int n = 0; n < 4; n++)
            #pragma unroll
            for (int r = 0; r < 4; r++) acc[m][n][r] = 0.f;

    #pragma unroll
    for (int ks8 = 0; ks8 < 8; ks8++) {
        const int k1 = ks8 * 8 + lt;
        unsigned bfr[4][2];
        #pragma unroll
        for (int n = 0; n < 4; n++) {
            const int n0 = wn * 32 + n * 8 + lg;
            bfr[n][0] = __float_as_uint(vs[k1 * 136 + n0]);
            bfr[n][1] = __float_as_uint(vs[(k1 + 4) * 136 + n0]);
        }
        #pragma unroll
        for (int m = 0; m < 2; m++) {
            const int m0 = wm * 32 + m * 16 + lg;
            const unsigned a0 = __float_as_uint(as[m0 * 68 + k1]);
            const unsigned a1 = __float_as_uint(as[(m0 + 8) * 68 + k1]);
            const unsigned a2 = __float_as_uint(as[m0 * 68 + k1 + 4]);
            const unsigned a3 = __float_as_uint(as[(m0 + 8) * 68 + k1 + 4]);
            #pragma unroll
            for (int n = 0; n < 4; n++)
                mma_tf32(acc[m][n][0], acc[m][n][1], acc[m][n][2], acc[m][n][3],
                         a0, a1, a2, a3, bfr[n][0], bfr[n][1]);
        }
    }

    const int h = bh & 7, b = bh >> 3;
    const int hc  = d0 >> 12;
    const int px0 = d0 & 4095;
    const int oc  = h * 8 + hc;
    #pragma unroll
    for (int m = 0; m < 2; m++) {
        #pragma unroll
        for (int n = 0; n < 4; n++) {
            const int row = wm * 32 + m * 16 + lg;
            const int dcol = wn * 32 + n * 8 + 2 * lt;
            {
                const int bt = b * 64 + row;
                float* dst = &g_y[((size_t)(bt * 64 + oc)) * 4096 + px0 + dcol];
                *(float2*)dst = make_float2(to_tf32f(acc[m][n][0]), to_tf32f(acc[m][n][1]));
            }
            {
                const int bt = b * 64 + row + 8;
                float* dst = &g_y[((size_t)(bt * 64 + oc)) * 4096 + px0 + dcol];
                *(float2*)dst = make_float2(to_tf32f(acc[m][n][2]), to_tf32f(acc[m][n][3]));
            }
        }
    }
}

// ============================================================================
// Kernel E: reduce 32 partials + causal softmax. Writes tf32-rounded att.
// grid (64 t, 16 bh), 64 thr.
// ============================================================================
__global__ void e_softmax()
{
    const int t = blockIdx.x, bh = blockIdx.y, k = threadIdx.x;
    __shared__ float red[64];
    float s = 0.f;
    #pragma unroll 8
    for (int ch = 0; ch < NCHUNK_; ch++)
        s += g_Sp[((size_t)(bh * NCHUNK_ + ch) * T_ + t) * T_ + k];
    s *= 0.005524271728019903f;   // 1/sqrt(32768)
    const bool valid = (k <= t);
    red[k] = valid ? s : -3.0e38f;
    __syncthreads();
    for (int off = 32; off; off >>= 1) {
        if (k < off) red[k] = fmaxf(red[k], red[k + off]);
        __syncthreads();
    }
    const float m = red[0];
    __syncthreads();
    const float e = valid ? expf(s - m) : 0.f;
    red[k] = e;
    __syncthreads();
    for (int off = 32; off; off >>= 1) {
        if (k < off) red[k] += red[k + off];
        __syncthreads();
    }
    g_att[((size_t)bh * T_ + t) * T_ + k] = to_tf32f(e / red[0]);
}

// ============================================================================
extern "C" void kernel_launch(void* const* d_in, const int* in_sizes, int n_in,
                              void* d_out, int out_size)
{
    const float* x  = (const float*)d_in[0];
    const float* wq = (const float*)d_in[1];
    const float* bq = (const float*)d_in[2];
    const float* wk = (const float*)d_in[3];
    const float* bk = (const float*)d_in[4];
    const float* wv = (const float*)d_in[5];
    const float* bv = (const float*)d_in[6];
    const float* wo = (const float*)d_in[7];
    const float* bo = (const float*)d_in[8];
    float* out = (float*)d_out;

    const int SM1 = (14976 + XSZQ_ + 96) * 4;       // 86400  -> 2 blocks/SM
    const int SM2 = (8448 + 8448) * 4;              // 67584  -> 2 blocks/SM
    const int SM4 = (4352 + 8704) * 4;              // 52224  -> 4 blocks/SM
    const int SM5 = (41472 + 2 * XSZB_ + 64) * 4;   // 218368 -> 1 block/SM

    cudaFuncSetAttribute(a_qkv_tc,   cudaFuncAttributeMaxDynamicSharedMemorySize, SM1);
    cudaFuncSetAttribute(c_scores_tc,cudaFuncAttributeMaxDynamicSharedMemorySize, SM2);
    cudaFuncSetAttribute(d_av_tc,    cudaFuncAttributeMaxDynamicSharedMemorySize, SM4);
    cudaFuncSetAttribute(b_convo_tc, cudaFuncAttributeMaxDynamicSharedMemorySize, SM5);

    a_qkv_tc   <<<dim3(4, 128, 2),   256, SM1>>>(x, wq, bq, wk, bk, wv, bv);
    c_scores_tc<<<dim3(NCHUNK_, 16), 256, SM2>>>();
    e_softmax  <<<dim3(64, 16),      64>>>();
    d_av_tc    <<<dim3(256, 16),     256, SM4>>>();
    b_convo_tc <<<dim3(4, 128),      256, SM5>>>(wo, bo, out);
}